// round 14
// baseline (speedup 1.0000x reference)
#include <cuda_runtime.h>
#include <cuda_fp16.h>
#include <mma.h>
#include <cstdint>

using namespace nvcuda;

#define DIM_IN  128
#define DIM_HID 256
#define DIM_OUT 128
#define NEXP    8
#define MAXN    65536
#define MAXROWS (2 * MAXN)
#define MAXTILES (MAXROWS / 128 + NEXP)

// ---------------- device scratch ----------------
__device__ int    g_counts[NEXP];
__device__ int    g_cursor[NEXP];
__device__ int    g_numTiles;
__device__ int    g_tileExpert[MAXTILES];
__device__ int    g_tileStart[MAXTILES];
__device__ int    g_tileRows[MAXTILES];
__device__ int    g_tokE[MAXN];
__device__ float2 g_tokW[MAXN];
__device__ int    g_rowToken[MAXROWS];
__device__ float  g_rowW[MAXROWS];

__device__ __align__(16) __half g_xf[MAXN * DIM_IN];
__device__ __align__(16) __half g_w1f[NEXP * DIM_IN * DIM_HID];  // [e][k=128][n=256]
__device__ __align__(16) __half g_w2f[NEXP * DIM_HID * DIM_OUT]; // [e][k=256][n=128]

__device__ __forceinline__ uint32_t packh2(float a, float b) {
    __half2 h = __floats2half2_rn(a, b);
    return *reinterpret_cast<uint32_t*>(&h);
}

// ---------------- kernel: weight fp16 convert + zero counts ----------------
__global__ void __launch_bounds__(256) moe_prep(
    const float* __restrict__ W1, const float* __restrict__ W2)
{
    int idx = blockIdx.x * 256 + threadIdx.x;          // 0 .. 65535
    if (blockIdx.x == 0 && threadIdx.x < NEXP) g_counts[threadIdx.x] = 0;
    if (idx < 65536) {
        float4 v = reinterpret_cast<const float4*>(W1)[idx];
        reinterpret_cast<uint2*>(g_w1f)[idx] = make_uint2(packh2(v.x, v.y), packh2(v.z, v.w));
        float4 w = reinterpret_cast<const float4*>(W2)[idx];
        reinterpret_cast<uint2*>(g_w2f)[idx] = make_uint2(packh2(w.x, w.y), packh2(w.z, w.w));
    }
}

// ---------------- kernel: gate (+ X fp16 + output zeroing) ----------------
__global__ void __launch_bounds__(256) moe_gate(
    const float* __restrict__ x, const float* __restrict__ Wp,
    const float* __restrict__ bp, const float* __restrict__ Ee,
    float* __restrict__ outbuf, long zero_lo, long zero_hi,
    float* __restrict__ pout, int n)
{
    __shared__ float WpS[DIM_IN * 64];
    __shared__ float EeS[64 * NEXP];
    __shared__ float hS[8][64];
    __shared__ float pS[8][8];
    __shared__ int   cntS[NEXP];

    int tid = threadIdx.x, warp = tid >> 5, lane = tid & 31;
    for (int i = tid; i < DIM_IN * 64; i += 256) WpS[i] = Wp[i];
    for (int i = tid; i < 64 * NEXP; i += 256)   EeS[i] = Ee[i];
    if (tid < NEXP) cntS[tid] = 0;
    if (blockIdx.x == 0 && tid == 0) {
        for (long i = zero_lo; i < zero_hi; i++) outbuf[i] = 0.f;
    }
    __syncthreads();

    const float4 z4 = make_float4(0.f, 0.f, 0.f, 0.f);

    for (int tok = blockIdx.x * 8 + warp; tok < n; tok += gridDim.x * 8) {
        float xr[4];
        #pragma unroll
        for (int i = 0; i < 4; i++) xr[i] = x[(long)tok * DIM_IN + lane + 32 * i];

        reinterpret_cast<float4*>(outbuf + (long)tok * DIM_OUT)[lane] = z4;

        #pragma unroll
        for (int i = 0; i < 4; i++)
            g_xf[(long)tok * DIM_IN + lane + 32 * i] = __float2half_rn(xr[i]);

        float h0 = bp[lane], h1 = bp[lane + 32];
        #pragma unroll
        for (int d = 0; d < DIM_IN; d++) {
            float xd = __shfl_sync(0xffffffffu, xr[d >> 5], d & 31);
            h0 += xd * WpS[d * 64 + lane];
            h1 += xd * WpS[d * 64 + lane + 32];
        }
        hS[warp][lane] = h0;
        hS[warp][lane + 32] = h1;
        __syncwarp();

        if (lane < NEXP) {
            float lg = 0.f;
            #pragma unroll
            for (int e2 = 0; e2 < 64; e2++) lg += hS[warp][e2] * EeS[e2 * NEXP + lane];
            float p = 1.f / (1.f + expf(-lg * 0.2f));   // tau = 5
            pS[warp][lane] = p;
            if (pout) pout[(long)tok * NEXP + lane] = p;
        }
        __syncwarp();

        if (lane == 0) {
            float v0 = -1.f, v1 = -1.f; int i0 = 0, i1 = 0;
            #pragma unroll
            for (int j = 0; j < NEXP; j++) {
                float pv = pS[warp][j];
                if (pv > v0) { v1 = v0; i1 = i0; v0 = pv; i0 = j; }
                else if (pv > v1) { v1 = pv; i1 = j; }
            }
            float s = v0 + v1 + 1e-10f;
            g_tokE[tok] = i0 | (i1 << 8);
            g_tokW[tok] = make_float2(v0 / s, v1 / s);
            atomicAdd(&cntS[i0], 1);
            atomicAdd(&cntS[i1], 1);
        }
        __syncwarp();
    }
    __syncthreads();
    if (tid < NEXP) atomicAdd(&g_counts[tid], cntS[tid]);
}

// ---------------- kernel: scan + tile map (128-row tiles) ----------------
__global__ void moe_build() {
    if (threadIdx.x == 0) {
        int off = 0, tile = 0;
        for (int e = 0; e < NEXP; e++) {
            int c = g_counts[e];
            g_cursor[e] = off;
            for (int t = 0; t < c && tile < MAXTILES; t += 128) {
                g_tileExpert[tile] = e;
                g_tileStart[tile]  = off + t;
                g_tileRows[tile]   = min(128, c - t);
                tile++;
            }
            off += c;
        }
        g_numTiles = tile;
    }
}

// ---------------- kernel: scatter ----------------
__global__ void __launch_bounds__(256) moe_scatter(int n) {
    __shared__ int cnt[NEXP];
    __shared__ int base[NEXP];
    int tid = threadIdx.x;
    if (tid < NEXP) cnt[tid] = 0;
    __syncthreads();

    int tok = blockIdx.x * 256 + tid;
    int e0 = 0, e1 = 0, r0 = 0, r1 = 0; float2 w = make_float2(0.f, 0.f);
    bool ok = (tok < n);
    if (ok) {
        int e01 = g_tokE[tok];
        w = g_tokW[tok];
        e0 = e01 & 255; e1 = (e01 >> 8) & 255;
        r0 = atomicAdd(&cnt[e0], 1);
        r1 = atomicAdd(&cnt[e1], 1);
    }
    __syncthreads();
    if (tid < NEXP) base[tid] = atomicAdd(&g_cursor[tid], cnt[tid]);
    __syncthreads();
    if (ok) {
        int p0 = base[e0] + r0; g_rowToken[p0] = tok; g_rowW[p0] = w.x;
        int p1 = base[e1] + r1; g_rowToken[p1] = tok; g_rowW[p1] = w.y;
    }
}

// ---------------- kernel: expert GEMM (fp16, 128-row tiles, 2 CTAs/SM) ----------------
using FragA = wmma::fragment<wmma::matrix_a, 16, 16, 16, __half, wmma::row_major>;
using FragB = wmma::fragment<wmma::matrix_b, 16, 16, 16, __half, wmma::row_major>;
using FragC = wmma::fragment<wmma::accumulator, 16, 16, 16, float>;

#define LDX 136           // X / W2-chunk plane: 128 x 136 half
#define LDW 264           // W1 / H plane:       128 x 264 half
#define XB  (128 * LDX * 2)   // 34816 B
#define WB  (128 * LDW * 2)   // 67584 B
#define SMEM_EXP (XB + WB)    // 102400 B -> 2 CTAs/SM
#define NTHR 256

__global__ void __launch_bounds__(NTHR, 2) moe_expert(
    const float* __restrict__ b1, const float* __restrict__ b2,
    float* __restrict__ out)
{
    int tile = blockIdx.x;
    if (tile >= g_numTiles) return;
    int e        = g_tileExpert[tile];
    int rowStart = g_tileStart[tile];
    int nRows    = g_tileRows[tile];

    extern __shared__ __align__(16) unsigned char sm[];
    __half* xr = (__half*)sm;                 // 128 x LDX (X, later W2 k-chunks)
    __half* hw = (__half*)(sm + XB);          // 128 x LDW (W1, later H)
    float* stage = (float*)sm;                // 128 x 68 fp32 = 34816 B over xr
    float* stC   = (float*)hw;                // 128 x 132 fp32 = 67584 B over hw

    __shared__ int   tokS[128];
    __shared__ float wS[128];
    __shared__ float b1s[256];
    __shared__ float b2s[128];

    int tid = threadIdx.x, warp = tid >> 5;
    int wm = warp >> 1, wn = warp & 1;        // 4 x 2 warp grid
    int m0 = wm * 32;

    if (tid < 128) {
        int tok = -1; float w = 0.f;
        if (tid < nRows) { tok = g_rowToken[rowStart + tid]; w = g_rowW[rowStart + tid]; }
        tokS[tid] = tok; wS[tid] = w;
        b2s[tid] = b2[(long)e * DIM_OUT + tid];
    }
    b1s[tid] = b1[(long)e * DIM_HID + tid];
    __syncthreads();

    // ---- fill X (gathered fp16) ----
    const uint4* x4 = (const uint4*)g_xf;
    #pragma unroll 4
    for (int i = tid; i < 128 * 16; i += NTHR) {
        int r = i >> 4, u = i & 15;
        uint4 v = make_uint4(0, 0, 0, 0);
        int tok = tokS[r];
        if (tok >= 0) v = x4[(long)tok * 16 + u];
        *reinterpret_cast<uint4*>(&xr[r * LDX + u * 8]) = v;
    }
    // ---- fill W1 [k=128][n=256] ----
    const uint4* w14 = (const uint4*)(g_w1f + (long)e * DIM_IN * DIM_HID);
    #pragma unroll 4
    for (int i = tid; i < 128 * 32; i += NTHR) {
        int r = i >> 5, u = i & 31;
        *reinterpret_cast<uint4*>(&hw[r * LDW + u * 8]) = w14[i];
    }
    __syncthreads();

    // ---- GEMM1: Hraw[128x256] = X @ W1 ; warp tile 32 x 128 ----
    FragC acc[2][8];
    #pragma unroll
    for (int mi = 0; mi < 2; mi++)
        #pragma unroll
        for (int nt = 0; nt < 8; nt++) wmma::fill_fragment(acc[mi][nt], 0.f);

    int nbase = wn * 128;
    #pragma unroll
    for (int ks = 0; ks < 8; ks++) {
        FragA a[2];
        #pragma unroll
        for (int mi = 0; mi < 2; mi++)
            wmma::load_matrix_sync(a[mi], &xr[(m0 + mi * 16) * LDX + ks * 16], LDX);
        #pragma unroll
        for (int nt = 0; nt < 8; nt++) {
            FragB b;
            wmma::load_matrix_sync(b, &hw[(ks * 16) * LDW + nbase + nt * 16], LDW);
            #pragma unroll
            for (int mi = 0; mi < 2; mi++)
                wmma::mma_sync(acc[mi][nt], a[mi], b, acc[mi][nt]);
        }
    }
    __syncthreads();   // X and W1 fully consumed

    // ---- H = relu(acc + b1): 4 phases of 64 cols, fp32 stage in dead X region ----
    #pragma unroll
    for (int p = 0; p < 4; p++) {
        if (wn == (p >> 1)) {
            #pragma unroll
            for (int mi = 0; mi < 2; mi++)
                #pragma unroll
                for (int j = 0; j < 4; j++)
                    wmma::store_matrix_sync(&stage[(m0 + mi * 16) * 68 + j * 16],
                                            acc[mi][(p & 1) * 4 + j], 68, wmma::mem_row_major);
        }
        __syncthreads();
        #pragma unroll 4
        for (int i = tid; i < 128 * 64; i += NTHR) {
            int r = i >> 6, c = i & 63;
            float v = stage[r * 68 + c] + b1s[p * 64 + c];
            v = v > 0.f ? v : 0.f;
            hw[r * LDW + p * 64 + c] = __float2half_rn(v);
        }
        __syncthreads();
    }

    // ---- GEMM2: C[128x128] = H @ W2, two 128-row K-chunks through dead X region ----
    FragC acc2[2][4];
    #pragma unroll
    for (int mi = 0; mi < 2; mi++)
        #pragma unroll
        for (int nt = 0; nt < 4; nt++) wmma::fill_fragment(acc2[mi][nt], 0.f);

    const uint4* w24 = (const uint4*)(g_w2f + (long)e * DIM_HID * DIM_OUT);
    #pragma unroll
    for (int ch = 0; ch < 2; ch++) {
        #pragma unroll 2
        for (int i = tid; i < 128 * 16; i += NTHR) {
            int r = i >> 4, u = i & 15;
            *reinterpret_cast<uint4*>(&xr[r * LDX + u * 8]) = w24[(ch * 128 + r) * 16 + u];
        }
        __syncthreads();
        #pragma unroll
        for (int ks = 0; ks < 8; ks++) {
            FragA a[2];
            #pragma unroll
            for (int mi = 0; mi < 2; mi++)
                wmma::load_matrix_sync(a[mi], &hw[(m0 + mi * 16) * LDW + ch * 128 + ks * 16], LDW);
            #pragma unroll
            for (int nt = 0; nt < 4; nt++) {
                FragB b;
                wmma::load_matrix_sync(b, &xr[(ks * 16) * LDX + wn * 64 + nt * 16], LDX);
                #pragma unroll
                for (int mi = 0; mi < 2; mi++)
                    wmma::mma_sync(acc2[mi][nt], a[mi], b, acc2[mi][nt]);
            }
        }
        __syncthreads();
    }

    // ---- epilogue: stage C (over dead H) then weighted atomics ----
    #pragma unroll
    for (int mi = 0; mi < 2; mi++)
        #pragma unroll
        for (int nt = 0; nt < 4; nt++)
            wmma::store_matrix_sync(&stC[(m0 + mi * 16) * 132 + wn * 64 + nt * 16],
                                    acc2[mi][nt], 132, wmma::mem_row_major);
    __syncthreads();

    #pragma unroll 4
    for (int i = tid; i < 128 * DIM_OUT; i += NTHR) {
        int r = i >> 7, c = i & 127;
        int tok = tokS[r];
        if (tok >= 0)
            atomicAdd(&out[(long)tok * DIM_OUT + c],
                      wS[r] * (stC[r * 132 + c] + b2s[c]));
    }
}

// ---------------- launch ----------------
extern "C" void kernel_launch(void* const* d_in, const int* in_sizes, int n_in,
                              void* d_out, int out_size) {
    const float* x  = (const float*)d_in[0];
    const float* Wp = (const float*)d_in[1];
    const float* bp = (const float*)d_in[2];
    const float* Ee = (const float*)d_in[3];
    const float* W1 = (const float*)d_in[4];
    const float* b1 = (const float*)d_in[5];
    const float* W2 = (const float*)d_in[6];
    const float* b2 = (const float*)d_in[7];
    float* out = (float*)d_out;

    int n = in_sizes[0] / DIM_IN;

    float* pout = nullptr;
    long need = (long)n * DIM_OUT + (long)n * NEXP;
    long zlo = (long)n * DIM_OUT, zhi = (long)out_size;
    if ((long)out_size >= need) {
        pout = out + ((long)out_size - (long)n * NEXP);
        zhi = (long)out_size - (long)n * NEXP;
    }

    moe_prep<<<256, 256>>>(W1, W2);
    moe_gate<<<1024, 256>>>(x, Wp, bp, Ee, out, zlo, zhi, pout, n);
    moe_build<<<1, 1>>>();
    moe_scatter<<<(n + 255) / 256, 256>>>(n);

    int tiles = (2 * n + 127) / 128 + NEXP;
    cudaFuncSetAttribute(moe_expert, cudaFuncAttributeMaxDynamicSharedMemorySize, SMEM_EXP);
    moe_expert<<<tiles, NTHR, SMEM_EXP>>>(b1, b2, out);
}

// round 15
// speedup vs baseline: 1.1361x; 1.1361x over previous
#include <cuda_runtime.h>
#include <cuda_fp16.h>
#include <mma.h>
#include <cstdint>

using namespace nvcuda;

#define DIM_IN  128
#define DIM_HID 256
#define DIM_OUT 128
#define NEXP    8
#define MAXN    65536
#define MAXROWS (2 * MAXN)
#define MAXTILES (MAXROWS / 128 + NEXP)

// ---------------- device scratch ----------------
__device__ int    g_counts[NEXP];
__device__ int    g_cursor[NEXP];
__device__ int    g_numTiles;
__device__ int    g_tileExpert[MAXTILES];
__device__ int    g_tileStart[MAXTILES];
__device__ int    g_tileRows[MAXTILES];
__device__ int    g_tokE[MAXN];
__device__ float2 g_tokW[MAXN];
__device__ int    g_rowToken[MAXROWS];
__device__ float  g_rowW[MAXROWS];

__device__ __align__(16) __half g_xf[MAXN * DIM_IN];
__device__ __align__(16) __half g_w1f[NEXP * DIM_IN * DIM_HID];  // [e][k=128][n=256]
__device__ __align__(16) __half g_w2f[NEXP * DIM_HID * DIM_OUT]; // [e][k=256][n=128]

__device__ __forceinline__ uint32_t packh2(float a, float b) {
    __half2 h = __floats2half2_rn(a, b);
    return *reinterpret_cast<uint32_t*>(&h);
}

// ---------------- kernel: weight fp16 convert + zero counts ----------------
__global__ void __launch_bounds__(256) moe_prep(
    const float* __restrict__ W1, const float* __restrict__ W2)
{
    int idx = blockIdx.x * 256 + threadIdx.x;          // 0 .. 65535
    if (blockIdx.x == 0 && threadIdx.x < NEXP) g_counts[threadIdx.x] = 0;
    if (idx < 65536) {
        float4 v = reinterpret_cast<const float4*>(W1)[idx];
        reinterpret_cast<uint2*>(g_w1f)[idx] = make_uint2(packh2(v.x, v.y), packh2(v.z, v.w));
        float4 w = reinterpret_cast<const float4*>(W2)[idx];
        reinterpret_cast<uint2*>(g_w2f)[idx] = make_uint2(packh2(w.x, w.y), packh2(w.z, w.w));
    }
}

// ---------------- kernel: gate (+ X fp16 + output zeroing) ----------------
__global__ void __launch_bounds__(256) moe_gate(
    const float* __restrict__ x, const float* __restrict__ Wp,
    const float* __restrict__ bp, const float* __restrict__ Ee,
    float* __restrict__ outbuf, long zero_lo, long zero_hi,
    float* __restrict__ pout, int n)
{
    __shared__ float WpS[DIM_IN * 64];
    __shared__ float EeS[64 * NEXP];
    __shared__ float hS[8][64];
    __shared__ float pS[8][8];
    __shared__ int   cntS[NEXP];

    int tid = threadIdx.x, warp = tid >> 5, lane = tid & 31;
    for (int i = tid; i < DIM_IN * 64; i += 256) WpS[i] = Wp[i];
    for (int i = tid; i < 64 * NEXP; i += 256)   EeS[i] = Ee[i];
    if (tid < NEXP) cntS[tid] = 0;
    if (blockIdx.x == 0 && tid == 0) {
        for (long i = zero_lo; i < zero_hi; i++) outbuf[i] = 0.f;
    }
    __syncthreads();

    const float4 z4 = make_float4(0.f, 0.f, 0.f, 0.f);

    for (int tok = blockIdx.x * 8 + warp; tok < n; tok += gridDim.x * 8) {
        float xr[4];
        #pragma unroll
        for (int i = 0; i < 4; i++) xr[i] = x[(long)tok * DIM_IN + lane + 32 * i];

        reinterpret_cast<float4*>(outbuf + (long)tok * DIM_OUT)[lane] = z4;

        #pragma unroll
        for (int i = 0; i < 4; i++)
            g_xf[(long)tok * DIM_IN + lane + 32 * i] = __float2half_rn(xr[i]);

        float h0 = bp[lane], h1 = bp[lane + 32];
        #pragma unroll
        for (int d = 0; d < DIM_IN; d++) {
            float xd = __shfl_sync(0xffffffffu, xr[d >> 5], d & 31);
            h0 += xd * WpS[d * 64 + lane];
            h1 += xd * WpS[d * 64 + lane + 32];
        }
        hS[warp][lane] = h0;
        hS[warp][lane + 32] = h1;
        __syncwarp();

        if (lane < NEXP) {
            float lg = 0.f;
            #pragma unroll
            for (int e2 = 0; e2 < 64; e2++) lg += hS[warp][e2] * EeS[e2 * NEXP + lane];
            float p = 1.f / (1.f + expf(-lg * 0.2f));   // tau = 5
            pS[warp][lane] = p;
            if (pout) pout[(long)tok * NEXP + lane] = p;
        }
        __syncwarp();

        if (lane == 0) {
            float v0 = -1.f, v1 = -1.f; int i0 = 0, i1 = 0;
            #pragma unroll
            for (int j = 0; j < NEXP; j++) {
                float pv = pS[warp][j];
                if (pv > v0) { v1 = v0; i1 = i0; v0 = pv; i0 = j; }
                else if (pv > v1) { v1 = pv; i1 = j; }
            }
            float s = v0 + v1 + 1e-10f;
            g_tokE[tok] = i0 | (i1 << 8);
            g_tokW[tok] = make_float2(v0 / s, v1 / s);
            atomicAdd(&cntS[i0], 1);
            atomicAdd(&cntS[i1], 1);
        }
        __syncwarp();
    }
    __syncthreads();
    if (tid < NEXP) atomicAdd(&g_counts[tid], cntS[tid]);
}

// ---------------- kernel: scan + tile map (128-row tiles) ----------------
__global__ void moe_build() {
    if (threadIdx.x == 0) {
        int off = 0, tile = 0;
        for (int e = 0; e < NEXP; e++) {
            int c = g_counts[e];
            g_cursor[e] = off;
            for (int t = 0; t < c && tile < MAXTILES; t += 128) {
                g_tileExpert[tile] = e;
                g_tileStart[tile]  = off + t;
                g_tileRows[tile]   = min(128, c - t);
                tile++;
            }
            off += c;
        }
        g_numTiles = tile;
    }
}

// ---------------- kernel: scatter ----------------
__global__ void __launch_bounds__(256) moe_scatter(int n) {
    __shared__ int cnt[NEXP];
    __shared__ int base[NEXP];
    int tid = threadIdx.x;
    if (tid < NEXP) cnt[tid] = 0;
    __syncthreads();

    int tok = blockIdx.x * 256 + tid;
    int e0 = 0, e1 = 0, r0 = 0, r1 = 0; float2 w = make_float2(0.f, 0.f);
    bool ok = (tok < n);
    if (ok) {
        int e01 = g_tokE[tok];
        w = g_tokW[tok];
        e0 = e01 & 255; e1 = (e01 >> 8) & 255;
        r0 = atomicAdd(&cnt[e0], 1);
        r1 = atomicAdd(&cnt[e1], 1);
    }
    __syncthreads();
    if (tid < NEXP) base[tid] = atomicAdd(&g_cursor[tid], cnt[tid]);
    __syncthreads();
    if (ok) {
        int p0 = base[e0] + r0; g_rowToken[p0] = tok; g_rowW[p0] = w.x;
        int p1 = base[e1] + r1; g_rowToken[p1] = tok; g_rowW[p1] = w.y;
    }
}

// ---- kernel: persistent expert GEMM (fp16, 512 thr, contiguous chunks, W1 cached) ----
using FragA = wmma::fragment<wmma::matrix_a, 16, 16, 16, __half, wmma::row_major>;
using FragB = wmma::fragment<wmma::matrix_b, 16, 16, 16, __half, wmma::row_major>;
using FragC = wmma::fragment<wmma::accumulator, 16, 16, 16, float>;

#define LDX 136           // X / W2-chunk / fp32-stage region: 128 x 136 half
#define LDW 264           // W1 region & H region: 128 x 264 half each
#define XB  (128 * LDX * 2)   // 34816 B
#define WB  (128 * LDW * 2)   // 67584 B
#define SMEM_EXP (XB + 2 * WB)   // 170 KB -> 1 CTA/SM
#define NTHR 512

__global__ void __launch_bounds__(NTHR, 1) moe_expert(
    const float* __restrict__ b1, const float* __restrict__ b2,
    float* __restrict__ out)
{
    extern __shared__ __align__(16) unsigned char sm[];
    __half* xr = (__half*)sm;                 // X / fp32 stage / W2 chunks
    __half* w1 = (__half*)(sm + XB);          // W1 (cached per expert)
    __half* hh = (__half*)(sm + XB + WB);     // H  (fp16) / epilogue fp32 stage
    float* stage = (float*)xr;                // 128 x 68 fp32 over xr
    float* stC   = (float*)hh;                // 128 x 132 fp32 over hh

    __shared__ int   tokS[128];
    __shared__ float wS[128];
    __shared__ float b1s[256];
    __shared__ float b2s[128];

    int tid = threadIdx.x, warp = tid >> 5;
    int wm = warp >> 2, wn = warp & 3;        // 4 x 4 warp grid
    int m0 = wm * 32;

    int numTiles = g_numTiles;
    int chunk = (numTiles + gridDim.x - 1) / gridDim.x;
    int tBeg = blockIdx.x * chunk;
    int tEnd = min(tBeg + chunk, numTiles);

    const uint4* x4 = (const uint4*)g_xf;
    int eCur = -1;

    for (int t = tBeg; t < tEnd; t++) {
        int e        = g_tileExpert[t];
        int rowStart = g_tileStart[t];
        int nRows    = g_tileRows[t];

        __syncthreads();   // previous tile fully done with smem
        if (tid < 128) {
            int tok = -1; float w = 0.f;
            if (tid < nRows) { tok = g_rowToken[rowStart + tid]; w = g_rowW[rowStart + tid]; }
            tokS[tid] = tok; wS[tid] = w;
        } else if (tid < 256) {
            b2s[tid - 128] = b2[(long)e * DIM_OUT + tid - 128];
        } else if (tid < 512) {
            b1s[tid - 256] = b1[(long)e * DIM_HID + tid - 256];
        }
        __syncthreads();

        // ---- fill X (gathered fp16) ----
        #pragma unroll 2
        for (int i = tid; i < 128 * 16; i += NTHR) {
            int r = i >> 4, u = i & 15;
            uint4 v = make_uint4(0, 0, 0, 0);
            int tok = tokS[r];
            if (tok >= 0) v = x4[(long)tok * 16 + u];
            *reinterpret_cast<uint4*>(&xr[r * LDX + u * 8]) = v;
        }
        // ---- fill W1 only on expert change ----
        if (e != eCur) {
            const uint4* w14 = (const uint4*)(g_w1f + (long)e * DIM_IN * DIM_HID);
            #pragma unroll 4
            for (int i = tid; i < 128 * 32; i += NTHR) {
                int r = i >> 5, u = i & 31;
                *reinterpret_cast<uint4*>(&w1[r * LDW + u * 8]) = w14[i];
            }
            eCur = e;
        }
        __syncthreads();

        // ---- GEMM1: Hraw[128x256] = X @ W1 ; warp tile 32 x 64 ----
        FragC acc[2][4];
        #pragma unroll
        for (int mi = 0; mi < 2; mi++)
            #pragma unroll
            for (int nt = 0; nt < 4; nt++) wmma::fill_fragment(acc[mi][nt], 0.f);

        int nbase = wn * 64;
        #pragma unroll
        for (int ks = 0; ks < 8; ks++) {
            FragA a[2];
            #pragma unroll
            for (int mi = 0; mi < 2; mi++)
                wmma::load_matrix_sync(a[mi], &xr[(m0 + mi * 16) * LDX + ks * 16], LDX);
            #pragma unroll
            for (int nt = 0; nt < 4; nt++) {
                FragB b;
                wmma::load_matrix_sync(b, &w1[(ks * 16) * LDW + nbase + nt * 16], LDW);
                #pragma unroll
                for (int mi = 0; mi < 2; mi++)
                    wmma::mma_sync(acc[mi][nt], a[mi], b, acc[mi][nt]);
            }
        }
        __syncthreads();   // X consumed (stage overlays X region)

        // ---- H = relu(acc + b1): 4 phases of 64 cols, half2-vectorized convert ----
        #pragma unroll
        for (int p = 0; p < 4; p++) {
            if (wn == p) {
                #pragma unroll
                for (int mi = 0; mi < 2; mi++)
                    #pragma unroll
                    for (int j = 0; j < 4; j++)
                        wmma::store_matrix_sync(&stage[(m0 + mi * 16) * 68 + j * 16],
                                                acc[mi][j], 68, wmma::mem_row_major);
            }
            __syncthreads();
            #pragma unroll 2
            for (int i = tid; i < 128 * 32; i += NTHR) {      // pairs
                int r = i >> 5, c2 = i & 31;
                float2 v = *reinterpret_cast<const float2*>(&stage[r * 68 + c2 * 2]);
                float v0 = v.x + b1s[p * 64 + c2 * 2];
                float v1 = v.y + b1s[p * 64 + c2 * 2 + 1];
                v0 = v0 > 0.f ? v0 : 0.f;
                v1 = v1 > 0.f ? v1 : 0.f;
                *reinterpret_cast<__half2*>(&hh[r * LDW + p * 64 + c2 * 2]) =
                    __floats2half2_rn(v0, v1);
            }
            __syncthreads();
        }

        // ---- GEMM2: C[128x128] = H @ W2 ; two 128-row K-chunks through X region ----
        FragC acc2[2][2];
        #pragma unroll
        for (int mi = 0; mi < 2; mi++)
            #pragma unroll
            for (int nt = 0; nt < 2; nt++) wmma::fill_fragment(acc2[mi][nt], 0.f);

        const uint4* w24 = (const uint4*)(g_w2f + (long)e * DIM_HID * DIM_OUT);
        #pragma unroll
        for (int ch = 0; ch < 2; ch++) {
            for (int i = tid; i < 128 * 16; i += NTHR) {
                int r = i >> 4, u = i & 15;
                *reinterpret_cast<uint4*>(&xr[r * LDX + u * 8]) = w24[(ch * 128 + r) * 16 + u];
            }
            __syncthreads();
            #pragma unroll
            for (int ks = 0; ks < 8; ks++) {
                FragA a[2];
                #pragma unroll
                for (int mi = 0; mi < 2; mi++)
                    wmma::load_matrix_sync(a[mi], &hh[(m0 + mi * 16) * LDW + ch * 128 + ks * 16], LDW);
                #pragma unroll
                for (int nt = 0; nt < 2; nt++) {
                    FragB b;
                    wmma::load_matrix_sync(b, &xr[(ks * 16) * LDX + wn * 32 + nt * 16], LDX);
                    #pragma unroll
                    for (int mi = 0; mi < 2; mi++)
                        wmma::mma_sync(acc2[mi][nt], a[mi], b, acc2[mi][nt]);
                }
            }
            __syncthreads();
        }

        // ---- epilogue: stage C over dead H region, weighted atomics ----
        #pragma unroll
        for (int mi = 0; mi < 2; mi++)
            #pragma unroll
            for (int nt = 0; nt < 2; nt++)
                wmma::store_matrix_sync(&stC[(m0 + mi * 16) * 132 + wn * 32 + nt * 16],
                                        acc2[mi][nt], 132, wmma::mem_row_major);
        __syncthreads();

        #pragma unroll 2
        for (int i = tid; i < 128 * DIM_OUT; i += NTHR) {
            int r = i >> 7, c = i & 127;
            int tok = tokS[r];
            if (tok >= 0)
                atomicAdd(&out[(long)tok * DIM_OUT + c],
                          wS[r] * (stC[r * 132 + c] + b2s[c]));
        }
    }
}

// ---------------- launch ----------------
extern "C" void kernel_launch(void* const* d_in, const int* in_sizes, int n_in,
                              void* d_out, int out_size) {
    const float* x  = (const float*)d_in[0];
    const float* Wp = (const float*)d_in[1];
    const float* bp = (const float*)d_in[2];
    const float* Ee = (const float*)d_in[3];
    const float* W1 = (const float*)d_in[4];
    const float* b1 = (const float*)d_in[5];
    const float* W2 = (const float*)d_in[6];
    const float* b2 = (const float*)d_in[7];
    float* out = (float*)d_out;

    int n = in_sizes[0] / DIM_IN;

    float* pout = nullptr;
    long need = (long)n * DIM_OUT + (long)n * NEXP;
    long zlo = (long)n * DIM_OUT, zhi = (long)out_size;
    if ((long)out_size >= need) {
        pout = out + ((long)out_size - (long)n * NEXP);
        zhi = (long)out_size - (long)n * NEXP;
    }

    moe_prep<<<256, 256>>>(W1, W2);
    moe_gate<<<1024, 256>>>(x, Wp, bp, Ee, out, zlo, zhi, pout, n);
    moe_build<<<1, 1>>>();
    moe_scatter<<<(n + 255) / 256, 256>>>(n);

    cudaFuncSetAttribute(moe_expert, cudaFuncAttributeMaxDynamicSharedMemorySize, SMEM_EXP);
    moe_expert<<<152, NTHR, SMEM_EXP>>>(b1, b2, out);
}

// round 16
// speedup vs baseline: 1.1801x; 1.0388x over previous
#include <cuda_runtime.h>
#include <cuda_fp16.h>
#include <mma.h>
#include <cstdint>

using namespace nvcuda;

#define DIM_IN  128
#define DIM_HID 256
#define DIM_OUT 128
#define NEXP    8
#define MAXN    65536
#define MAXROWS (2 * MAXN)
#define MAXTILES (MAXROWS / 128 + NEXP)

// ---------------- device scratch ----------------
__device__ int    g_counts[NEXP];
__device__ int    g_cursor[NEXP];
__device__ int    g_numTiles;
__device__ int    g_tileExpert[MAXTILES];
__device__ int    g_tileStart[MAXTILES];
__device__ int    g_tileRows[MAXTILES];
__device__ int    g_tokE[MAXN];
__device__ float2 g_tokW[MAXN];
__device__ int    g_rowToken[MAXROWS];
__device__ float  g_rowW[MAXROWS];

__device__ __align__(16) __half g_xf[MAXN * DIM_IN];
__device__ __align__(16) __half g_w1f[NEXP * DIM_IN * DIM_HID];  // [e][k=128][n=256]
__device__ __align__(16) __half g_w2f[NEXP * DIM_HID * DIM_OUT]; // [e][k=256][n=128]

__device__ __forceinline__ uint32_t packh2(float a, float b) {
    __half2 h = __floats2half2_rn(a, b);
    return *reinterpret_cast<uint32_t*>(&h);
}

// ---------------- kernel: weight fp16 convert + zero counts ----------------
__global__ void __launch_bounds__(256) moe_prep(
    const float* __restrict__ W1, const float* __restrict__ W2)
{
    int idx = blockIdx.x * 256 + threadIdx.x;          // 0 .. 65535
    if (blockIdx.x == 0 && threadIdx.x < NEXP) g_counts[threadIdx.x] = 0;
    if (idx < 65536) {
        float4 v = reinterpret_cast<const float4*>(W1)[idx];
        reinterpret_cast<uint2*>(g_w1f)[idx] = make_uint2(packh2(v.x, v.y), packh2(v.z, v.w));
        float4 w = reinterpret_cast<const float4*>(W2)[idx];
        reinterpret_cast<uint2*>(g_w2f)[idx] = make_uint2(packh2(w.x, w.y), packh2(w.z, w.w));
    }
}

// ---------------- kernel: gate (+ X fp16 + output zeroing) ----------------
__global__ void __launch_bounds__(256) moe_gate(
    const float* __restrict__ x, const float* __restrict__ Wp,
    const float* __restrict__ bp, const float* __restrict__ Ee,
    float* __restrict__ outbuf, long zero_lo, long zero_hi,
    float* __restrict__ pout, int n)
{
    __shared__ float WpS[DIM_IN * 64];
    __shared__ float EeS[64 * NEXP];
    __shared__ float hS[8][64];
    __shared__ float pS[8][8];
    __shared__ int   cntS[NEXP];

    int tid = threadIdx.x, warp = tid >> 5, lane = tid & 31;
    for (int i = tid; i < DIM_IN * 64; i += 256) WpS[i] = Wp[i];
    for (int i = tid; i < 64 * NEXP; i += 256)   EeS[i] = Ee[i];
    if (tid < NEXP) cntS[tid] = 0;
    if (blockIdx.x == 0 && tid == 0) {
        for (long i = zero_lo; i < zero_hi; i++) outbuf[i] = 0.f;
    }
    __syncthreads();

    const float4 z4 = make_float4(0.f, 0.f, 0.f, 0.f);

    for (int tok = blockIdx.x * 8 + warp; tok < n; tok += gridDim.x * 8) {
        float xr[4];
        #pragma unroll
        for (int i = 0; i < 4; i++) xr[i] = x[(long)tok * DIM_IN + lane + 32 * i];

        reinterpret_cast<float4*>(outbuf + (long)tok * DIM_OUT)[lane] = z4;

        #pragma unroll
        for (int i = 0; i < 4; i++)
            g_xf[(long)tok * DIM_IN + lane + 32 * i] = __float2half_rn(xr[i]);

        float h0 = bp[lane], h1 = bp[lane + 32];
        #pragma unroll
        for (int d = 0; d < DIM_IN; d++) {
            float xd = __shfl_sync(0xffffffffu, xr[d >> 5], d & 31);
            h0 += xd * WpS[d * 64 + lane];
            h1 += xd * WpS[d * 64 + lane + 32];
        }
        hS[warp][lane] = h0;
        hS[warp][lane + 32] = h1;
        __syncwarp();

        if (lane < NEXP) {
            float lg = 0.f;
            #pragma unroll
            for (int e2 = 0; e2 < 64; e2++) lg += hS[warp][e2] * EeS[e2 * NEXP + lane];
            float p = 1.f / (1.f + expf(-lg * 0.2f));   // tau = 5
            pS[warp][lane] = p;
            if (pout) pout[(long)tok * NEXP + lane] = p;
        }
        __syncwarp();

        if (lane == 0) {
            float v0 = -1.f, v1 = -1.f; int i0 = 0, i1 = 0;
            #pragma unroll
            for (int j = 0; j < NEXP; j++) {
                float pv = pS[warp][j];
                if (pv > v0) { v1 = v0; i1 = i0; v0 = pv; i0 = j; }
                else if (pv > v1) { v1 = pv; i1 = j; }
            }
            float s = v0 + v1 + 1e-10f;
            g_tokE[tok] = i0 | (i1 << 8);
            g_tokW[tok] = make_float2(v0 / s, v1 / s);
            atomicAdd(&cntS[i0], 1);
            atomicAdd(&cntS[i1], 1);
        }
        __syncwarp();
    }
    __syncthreads();
    if (tid < NEXP) atomicAdd(&g_counts[tid], cntS[tid]);
}

// ---------------- kernel: scan + tile map (128-row tiles) ----------------
__global__ void moe_build() {
    if (threadIdx.x == 0) {
        int off = 0, tile = 0;
        for (int e = 0; e < NEXP; e++) {
            int c = g_counts[e];
            g_cursor[e] = off;
            for (int t = 0; t < c && tile < MAXTILES; t += 128) {
                g_tileExpert[tile] = e;
                g_tileStart[tile]  = off + t;
                g_tileRows[tile]   = min(128, c - t);
                tile++;
            }
            off += c;
        }
        g_numTiles = tile;
    }
}

// ---------------- kernel: scatter ----------------
__global__ void __launch_bounds__(256) moe_scatter(int n) {
    __shared__ int cnt[NEXP];
    __shared__ int base[NEXP];
    int tid = threadIdx.x;
    if (tid < NEXP) cnt[tid] = 0;
    __syncthreads();

    int tok = blockIdx.x * 256 + tid;
    int e0 = 0, e1 = 0, r0 = 0, r1 = 0; float2 w = make_float2(0.f, 0.f);
    bool ok = (tok < n);
    if (ok) {
        int e01 = g_tokE[tok];
        w = g_tokW[tok];
        e0 = e01 & 255; e1 = (e01 >> 8) & 255;
        r0 = atomicAdd(&cnt[e0], 1);
        r1 = atomicAdd(&cnt[e1], 1);
    }
    __syncthreads();
    if (tid < NEXP) base[tid] = atomicAdd(&g_cursor[tid], cnt[tid]);
    __syncthreads();
    if (ok) {
        int p0 = base[e0] + r0; g_rowToken[p0] = tok; g_rowW[p0] = w.x;
        int p1 = base[e1] + r1; g_rowToken[p1] = tok; g_rowW[p1] = w.y;
    }
}

// ---- kernel: persistent expert GEMM (fp16, bias-in-acc, fragment relu/convert) ----
using FragA  = wmma::fragment<wmma::matrix_a, 16, 16, 16, __half, wmma::row_major>;
using FragB  = wmma::fragment<wmma::matrix_b, 16, 16, 16, __half, wmma::row_major>;
using FragC  = wmma::fragment<wmma::accumulator, 16, 16, 16, float>;
using FragCh = wmma::fragment<wmma::accumulator, 16, 16, 16, __half>;

#define LDX 136           // X / W2-chunk region: 128 x 136 half
#define LDW 264           // W1 region & H region: 128 x 264 half each
#define XB  (128 * LDX * 2)   // 34816 B
#define WB  (128 * LDW * 2)   // 67584 B
#define B1B (16 * 256 * 4)    // 16384 B
#define B2B (16 * 128 * 4)    // 8192 B
#define SMEM_EXP (XB + 2 * WB + B1B + B2B)   // 194560 B -> 1 CTA/SM
#define NTHR 512

__global__ void __launch_bounds__(NTHR, 1) moe_expert(
    const float* __restrict__ b1, const float* __restrict__ b2,
    float* __restrict__ out)
{
    extern __shared__ __align__(16) unsigned char sm[];
    __half* xr  = (__half*)sm;                        // X / W2 chunks
    __half* w1  = (__half*)(sm + XB);                 // W1 (cached per expert)
    __half* hh  = (__half*)(sm + XB + WB);            // H (fp16) / epilogue fp32 stage
    float*  b1T = (float*)(sm + XB + 2 * WB);         // 16 x 256 bias tile
    float*  b2T = (float*)(sm + XB + 2 * WB + B1B);   // 16 x 128 bias tile
    float*  stC = (float*)hh;                         // 128 x 132 fp32 over hh

    __shared__ int   tokS[128];
    __shared__ float wS[128];

    int tid = threadIdx.x, warp = tid >> 5;
    int wm = warp >> 2, wn = warp & 3;        // 4 x 4 warp grid
    int m0 = wm * 32;

    int numTiles = g_numTiles;
    int chunk = (numTiles + gridDim.x - 1) / gridDim.x;
    int tBeg = blockIdx.x * chunk;
    int tEnd = min(tBeg + chunk, numTiles);

    const uint4* x4 = (const uint4*)g_xf;
    int eCur = -1;

    for (int t = tBeg; t < tEnd; t++) {
        int e        = g_tileExpert[t];
        int rowStart = g_tileStart[t];
        int nRows    = g_tileRows[t];

        __syncthreads();   // previous tile fully done with smem
        if (tid < 128) {
            int tok = -1; float w = 0.f;
            if (tid < nRows) { tok = g_rowToken[rowStart + tid]; w = g_rowW[rowStart + tid]; }
            tokS[tid] = tok; wS[tid] = w;
        }
        __syncthreads();

        // ---- fill X (gathered fp16) ----
        #pragma unroll 2
        for (int i = tid; i < 128 * 16; i += NTHR) {
            int r = i >> 4, u = i & 15;
            uint4 v = make_uint4(0, 0, 0, 0);
            int tok = tokS[r];
            if (tok >= 0) v = x4[(long)tok * 16 + u];
            *reinterpret_cast<uint4*>(&xr[r * LDX + u * 8]) = v;
        }
        // ---- on expert change: fill W1 + bias tiles ----
        if (e != eCur) {
            const uint4* w14 = (const uint4*)(g_w1f + (long)e * DIM_IN * DIM_HID);
            #pragma unroll 4
            for (int i = tid; i < 128 * 32; i += NTHR) {
                int r = i >> 5, u = i & 31;
                *reinterpret_cast<uint4*>(&w1[r * LDW + u * 8]) = w14[i];
            }
            for (int i = tid; i < 16 * 256; i += NTHR) b1T[i] = b1[(long)e * DIM_HID + (i & 255)];
            for (int i = tid; i < 16 * 128; i += NTHR) b2T[i] = b2[(long)e * DIM_OUT + (i & 127)];
            eCur = e;
        }
        __syncthreads();

        // ---- GEMM1: H[128x256] = relu(X @ W1 + b1) ; warp tile 32 x 64 ----
        FragC acc[2][4];
        int nbase = wn * 64;
        #pragma unroll
        for (int mi = 0; mi < 2; mi++)
            #pragma unroll
            for (int nt = 0; nt < 4; nt++)
                wmma::load_matrix_sync(acc[mi][nt], &b1T[nbase + nt * 16], 256, wmma::mem_row_major);

        #pragma unroll
        for (int ks = 0; ks < 8; ks++) {
            FragA a[2];
            #pragma unroll
            for (int mi = 0; mi < 2; mi++)
                wmma::load_matrix_sync(a[mi], &xr[(m0 + mi * 16) * LDX + ks * 16], LDX);
            #pragma unroll
            for (int nt = 0; nt < 4; nt++) {
                FragB b;
                wmma::load_matrix_sync(b, &w1[(ks * 16) * LDW + nbase + nt * 16], LDW);
                #pragma unroll
                for (int mi = 0; mi < 2; mi++)
                    wmma::mma_sync(acc[mi][nt], a[mi], b, acc[mi][nt]);
            }
        }
        __syncthreads();   // W1/X reads done everywhere before H overwrites hh? (hh separate) — sync for X reuse below

        // fragment-resident relu + fp16 convert, store straight into H
        #pragma unroll
        for (int mi = 0; mi < 2; mi++)
            #pragma unroll
            for (int nt = 0; nt < 4; nt++) {
                FragCh hc;
                #pragma unroll
                for (int j = 0; j < acc[mi][nt].num_elements; j++) {
                    float v = acc[mi][nt].x[j];
                    hc.x[j] = __float2half_rn(v > 0.f ? v : 0.f);
                }
                wmma::store_matrix_sync(&hh[(m0 + mi * 16) * LDW + nbase + nt * 16],
                                        hc, LDW, wmma::mem_row_major);
            }
        __syncthreads();

        // ---- GEMM2: C[128x128] = H @ W2 + b2 ; two 128-row K-chunks through X region ----
        FragC acc2[2][2];
        int nb2 = wn * 32;
        #pragma unroll
        for (int mi = 0; mi < 2; mi++)
            #pragma unroll
            for (int nt = 0; nt < 2; nt++)
                wmma::load_matrix_sync(acc2[mi][nt], &b2T[nb2 + nt * 16], 128, wmma::mem_row_major);

        const uint4* w24 = (const uint4*)(g_w2f + (long)e * DIM_HID * DIM_OUT);
        #pragma unroll
        for (int ch = 0; ch < 2; ch++) {
            for (int i = tid; i < 128 * 16; i += NTHR) {
                int r = i >> 4, u = i & 15;
                *reinterpret_cast<uint4*>(&xr[r * LDX + u * 8]) = w24[(ch * 128 + r) * 16 + u];
            }
            __syncthreads();
            #pragma unroll
            for (int ks = 0; ks < 8; ks++) {
                FragA a[2];
                #pragma unroll
                for (int mi = 0; mi < 2; mi++)
                    wmma::load_matrix_sync(a[mi], &hh[(m0 + mi * 16) * LDW + ch * 128 + ks * 16], LDW);
                #pragma unroll
                for (int nt = 0; nt < 2; nt++) {
                    FragB b;
                    wmma::load_matrix_sync(b, &xr[(ks * 16) * LDX + nb2 + nt * 16], LDX);
                    #pragma unroll
                    for (int mi = 0; mi < 2; mi++)
                        wmma::mma_sync(acc2[mi][nt], a[mi], b, acc2[mi][nt]);
                }
            }
            __syncthreads();
        }

        // ---- epilogue: stage C+b2 over dead H region, weighted atomics ----
        #pragma unroll
        for (int mi = 0; mi < 2; mi++)
            #pragma unroll
            for (int nt = 0; nt < 2; nt++)
                wmma::store_matrix_sync(&stC[(m0 + mi * 16) * 132 + nb2 + nt * 16],
                                        acc2[mi][nt], 132, wmma::mem_row_major);
        __syncthreads();

        #pragma unroll 2
        for (int i = tid; i < 128 * DIM_OUT; i += NTHR) {
            int r = i >> 7, c = i & 127;
            int tok = tokS[r];
            if (tok >= 0)
                atomicAdd(&out[(long)tok * DIM_OUT + c], wS[r] * stC[r * 132 + c]);
        }
    }
}

// ---------------- launch ----------------
extern "C" void kernel_launch(void* const* d_in, const int* in_sizes, int n_in,
                              void* d_out, int out_size) {
    const float* x  = (const float*)d_in[0];
    const float* Wp = (const float*)d_in[1];
    const float* bp = (const float*)d_in[2];
    const float* Ee = (const float*)d_in[3];
    const float* W1 = (const float*)d_in[4];
    const float* b1 = (const float*)d_in[5];
    const float* W2 = (const float*)d_in[6];
    const float* b2 = (const float*)d_in[7];
    float* out = (float*)d_out;

    int n = in_sizes[0] / DIM_IN;

    float* pout = nullptr;
    long need = (long)n * DIM_OUT + (long)n * NEXP;
    long zlo = (long)n * DIM_OUT, zhi = (long)out_size;
    if ((long)out_size >= need) {
        pout = out + ((long)out_size - (long)n * NEXP);
        zhi = (long)out_size - (long)n * NEXP;
    }

    moe_prep<<<256, 256>>>(W1, W2);
    moe_gate<<<1024, 256>>>(x, Wp, bp, Ee, out, zlo, zhi, pout, n);
    moe_build<<<1, 1>>>();
    moe_scatter<<<(n + 255) / 256, 256>>>(n);

    cudaFuncSetAttribute(moe_expert, cudaFuncAttributeMaxDynamicSharedMemorySize, SMEM_EXP);
    moe_expert<<<152, NTHR, SMEM_EXP>>>(b1, b2, out);
}

// round 17
// speedup vs baseline: 1.2391x; 1.0500x over previous
#include <cuda_runtime.h>
#include <cuda_fp16.h>
#include <mma.h>
#include <cstdint>

using namespace nvcuda;

#define DIM_IN  128
#define DIM_HID 256
#define DIM_OUT 128
#define NEXP    8
#define MAXN    65536
#define MAXROWS (2 * MAXN)
#define MAXTILES (MAXROWS / 128 + NEXP)

// ---------------- device scratch ----------------
__device__ int    g_counts[NEXP];
__device__ int    g_cursor[NEXP];
__device__ int    g_numTiles;
__device__ int    g_tileExpert[MAXTILES];
__device__ int    g_tileStart[MAXTILES];
__device__ int    g_tileRows[MAXTILES];
__device__ int    g_tokE[MAXN];
__device__ float2 g_tokW[MAXN];
__device__ int    g_rowToken[MAXROWS];
__device__ float  g_rowW[MAXROWS];

__device__ __align__(16) __half g_xf[MAXN * DIM_IN];
__device__ __align__(16) __half g_w1f[NEXP * DIM_IN * DIM_HID];  // [e][k=128][n=256]
__device__ __align__(16) __half g_w2f[NEXP * DIM_HID * DIM_OUT]; // [e][k=256][n=128]

__device__ __forceinline__ uint32_t packh2(float a, float b) {
    __half2 h = __floats2half2_rn(a, b);
    return *reinterpret_cast<uint32_t*>(&h);
}
__device__ __forceinline__ uint32_t smem_u32(const void* p) {
    uint32_t a;
    asm("{ .reg .u64 t; cvta.to.shared.u64 t, %1; cvt.u32.u64 %0, t; }" : "=r"(a) : "l"(p));
    return a;
}
#define CP_ASYNC16(dst, src) asm volatile("cp.async.cg.shared.global [%0], [%1], 16;" :: "r"(dst), "l"(src))
#define CP_COMMIT()          asm volatile("cp.async.commit_group;" ::: "memory")
#define CP_WAIT0()           asm volatile("cp.async.wait_group 0;" ::: "memory")
#define CP_WAIT1()           asm volatile("cp.async.wait_group 1;" ::: "memory")

// ---------------- kernel: weight fp16 convert + zero counts ----------------
__global__ void __launch_bounds__(256) moe_prep(
    const float* __restrict__ W1, const float* __restrict__ W2)
{
    int idx = blockIdx.x * 256 + threadIdx.x;          // 0 .. 65535
    if (blockIdx.x == 0 && threadIdx.x < NEXP) g_counts[threadIdx.x] = 0;
    if (idx < 65536) {
        float4 v = reinterpret_cast<const float4*>(W1)[idx];
        reinterpret_cast<uint2*>(g_w1f)[idx] = make_uint2(packh2(v.x, v.y), packh2(v.z, v.w));
        float4 w = reinterpret_cast<const float4*>(W2)[idx];
        reinterpret_cast<uint2*>(g_w2f)[idx] = make_uint2(packh2(w.x, w.y), packh2(w.z, w.w));
    }
}

// ---------------- kernel: gate (+ X fp16 + output zeroing) ----------------
__global__ void __launch_bounds__(256) moe_gate(
    const float* __restrict__ x, const float* __restrict__ Wp,
    const float* __restrict__ bp, const float* __restrict__ Ee,
    float* __restrict__ outbuf, long zero_lo, long zero_hi,
    float* __restrict__ pout, int n)
{
    __shared__ float WpS[DIM_IN * 64];
    __shared__ float EeS[64 * NEXP];
    __shared__ float hS[8][64];
    __shared__ float pS[8][8];
    __shared__ int   cntS[NEXP];

    int tid = threadIdx.x, warp = tid >> 5, lane = tid & 31;
    for (int i = tid; i < DIM_IN * 64; i += 256) WpS[i] = Wp[i];
    for (int i = tid; i < 64 * NEXP; i += 256)   EeS[i] = Ee[i];
    if (tid < NEXP) cntS[tid] = 0;
    if (blockIdx.x == 0 && tid == 0) {
        for (long i = zero_lo; i < zero_hi; i++) outbuf[i] = 0.f;
    }
    __syncthreads();

    const float4 z4 = make_float4(0.f, 0.f, 0.f, 0.f);

    for (int tok = blockIdx.x * 8 + warp; tok < n; tok += gridDim.x * 8) {
        float xr[4];
        #pragma unroll
        for (int i = 0; i < 4; i++) xr[i] = x[(long)tok * DIM_IN + lane + 32 * i];

        reinterpret_cast<float4*>(outbuf + (long)tok * DIM_OUT)[lane] = z4;

        #pragma unroll
        for (int i = 0; i < 4; i++)
            g_xf[(long)tok * DIM_IN + lane + 32 * i] = __float2half_rn(xr[i]);

        float h0 = bp[lane], h1 = bp[lane + 32];
        #pragma unroll
        for (int d = 0; d < DIM_IN; d++) {
            float xd = __shfl_sync(0xffffffffu, xr[d >> 5], d & 31);
            h0 += xd * WpS[d * 64 + lane];
            h1 += xd * WpS[d * 64 + lane + 32];
        }
        hS[warp][lane] = h0;
        hS[warp][lane + 32] = h1;
        __syncwarp();

        if (lane < NEXP) {
            float lg = 0.f;
            #pragma unroll
            for (int e2 = 0; e2 < 64; e2++) lg += hS[warp][e2] * EeS[e2 * NEXP + lane];
            float p = 1.f / (1.f + expf(-lg * 0.2f));   // tau = 5
            pS[warp][lane] = p;
            if (pout) pout[(long)tok * NEXP + lane] = p;
        }
        __syncwarp();

        if (lane == 0) {
            float v0 = -1.f, v1 = -1.f; int i0 = 0, i1 = 0;
            #pragma unroll
            for (int j = 0; j < NEXP; j++) {
                float pv = pS[warp][j];
                if (pv > v0) { v1 = v0; i1 = i0; v0 = pv; i0 = j; }
                else if (pv > v1) { v1 = pv; i1 = j; }
            }
            float s = v0 + v1 + 1e-10f;
            g_tokE[tok] = i0 | (i1 << 8);
            g_tokW[tok] = make_float2(v0 / s, v1 / s);
            atomicAdd(&cntS[i0], 1);
            atomicAdd(&cntS[i1], 1);
        }
        __syncwarp();
    }
    __syncthreads();
    if (tid < NEXP) atomicAdd(&g_counts[tid], cntS[tid]);
}

// ---------------- kernel: scan + tile map (128-row tiles) ----------------
__global__ void moe_build() {
    if (threadIdx.x == 0) {
        int off = 0, tile = 0;
        for (int e = 0; e < NEXP; e++) {
            int c = g_counts[e];
            g_cursor[e] = off;
            for (int t = 0; t < c && tile < MAXTILES; t += 128) {
                g_tileExpert[tile] = e;
                g_tileStart[tile]  = off + t;
                g_tileRows[tile]   = min(128, c - t);
                tile++;
            }
            off += c;
        }
        g_numTiles = tile;
    }
}

// ---------------- kernel: scatter ----------------
__global__ void __launch_bounds__(256) moe_scatter(int n) {
    __shared__ int cnt[NEXP];
    __shared__ int base[NEXP];
    int tid = threadIdx.x;
    if (tid < NEXP) cnt[tid] = 0;
    __syncthreads();

    int tok = blockIdx.x * 256 + tid;
    int e0 = 0, e1 = 0, r0 = 0, r1 = 0; float2 w = make_float2(0.f, 0.f);
    bool ok = (tok < n);
    if (ok) {
        int e01 = g_tokE[tok];
        w = g_tokW[tok];
        e0 = e01 & 255; e1 = (e01 >> 8) & 255;
        r0 = atomicAdd(&cnt[e0], 1);
        r1 = atomicAdd(&cnt[e1], 1);
    }
    __syncthreads();
    if (tid < NEXP) base[tid] = atomicAdd(&g_cursor[tid], cnt[tid]);
    __syncthreads();
    if (ok) {
        int p0 = base[e0] + r0; g_rowToken[p0] = tok; g_rowW[p0] = w.x;
        int p1 = base[e1] + r1; g_rowToken[p1] = tok; g_rowW[p1] = w.y;
    }
}

// ---- kernel: persistent expert GEMM (fp16, bias-in-acc, frag relu, cp.async pipeline) ----
using FragA  = wmma::fragment<wmma::matrix_a, 16, 16, 16, __half, wmma::row_major>;
using FragB  = wmma::fragment<wmma::matrix_b, 16, 16, 16, __half, wmma::row_major>;
using FragC  = wmma::fragment<wmma::accumulator, 16, 16, 16, float>;
using FragCh = wmma::fragment<wmma::accumulator, 16, 16, 16, __half>;

#define LDX 136           // X / W2-chunk layout: 128 x 136 half
#define LDW 264           // W1 / H layout:       128 x 264 half
#define XB  (128 * LDX * 2)   // 34816 B
#define WB  (128 * LDW * 2)   // 67584 B
#define B1B (16 * 256 * 4)    // 16384 B
#define B2B (16 * 128 * 4)    // 8192 B
// xr | w1 | hh | w2c | b1T | b2T  = 34816+67584+67584+34816+16384+8192 = 229376 B
#define SMEM_EXP (2 * XB + 2 * WB + B1B + B2B)
#define NTHR 512

__global__ void __launch_bounds__(NTHR, 1) moe_expert(
    const float* __restrict__ b1, const float* __restrict__ b2,
    float* __restrict__ out)
{
    extern __shared__ __align__(16) unsigned char sm[];
    __half* xr  = (__half*)sm;                            // X (prefetched across tiles)
    __half* w1  = (__half*)(sm + XB);                     // W1 (cached per expert)
    __half* hh  = (__half*)(sm + XB + WB);                // H (fp16) / epilogue fp32 stage
    __half* w2c = (__half*)(sm + XB + 2 * WB);            // W2 chunk buffer
    float*  b1T = (float*)(sm + 2 * XB + 2 * WB);         // 16 x 256 bias tile
    float*  b2T = (float*)(sm + 2 * XB + 2 * WB + B1B);   // 16 x 128 bias tile
    float*  stC = (float*)hh;

    __shared__ int   tokS[2][128];
    __shared__ float wS[2][128];

    int tid = threadIdx.x, warp = tid >> 5;
    int wm = warp >> 2, wn = warp & 3;        // 4 x 4 warp grid
    int m0 = wm * 32;

    int numTiles = g_numTiles;
    int chunk = (numTiles + gridDim.x - 1) / gridDim.x;
    int tBeg = blockIdx.x * chunk;
    int tEnd = min(tBeg + chunk, numTiles);
    if (tBeg >= tEnd) return;

    const uint4* x4 = (const uint4*)g_xf;
    uint32_t xru = smem_u32(xr);
    uint32_t w2u = smem_u32(w2c);
    int eCur = -1;

    // ---- prologue: meta + synchronous X fill for first tile ----
    if (tid < 128) {
        int rs = g_tileStart[tBeg], nr = g_tileRows[tBeg];
        int tok = -1; float w = 0.f;
        if (tid < nr) { tok = g_rowToken[rs + tid]; w = g_rowW[rs + tid]; }
        tokS[0][tid] = tok; wS[0][tid] = w;
    }
    __syncthreads();
    #pragma unroll 2
    for (int i = tid; i < 128 * 16; i += NTHR) {
        int r = i >> 4, u = i & 15;
        uint4 v = make_uint4(0, 0, 0, 0);
        int tok = tokS[0][r];
        if (tok >= 0) v = x4[(long)tok * 16 + u];
        *reinterpret_cast<uint4*>(&xr[r * LDX + u * 8]) = v;
    }

    int buf = 0;
    for (int t = tBeg; t < tEnd; t++, buf ^= 1) {
        int e  = g_tileExpert[t];
        int nb = buf ^ 1;

        CP_WAIT0();          // X for this tile fully arrived (prefetch or prologue)
        __syncthreads();

        // ---- on expert change: fill W1 + bias tiles ----
        if (e != eCur) {
            const uint4* w14 = (const uint4*)(g_w1f + (long)e * DIM_IN * DIM_HID);
            #pragma unroll 4
            for (int i = tid; i < 128 * 32; i += NTHR) {
                int r = i >> 5, u = i & 31;
                *reinterpret_cast<uint4*>(&w1[r * LDW + u * 8]) = w14[i];
            }
            for (int i = tid; i < 16 * 256; i += NTHR) b1T[i] = b1[(long)e * DIM_HID + (i & 255)];
            for (int i = tid; i < 16 * 128; i += NTHR) b2T[i] = b2[(long)e * DIM_OUT + (i & 127)];
            eCur = e;
            __syncthreads();
        }

        // ---- issue W2 chunk0 prefetch (hidden under GEMM1) ----
        const uint4* w24 = (const uint4*)(g_w2f + (long)e * DIM_HID * DIM_OUT);
        for (int i = tid; i < 128 * 16; i += NTHR) {
            int r = i >> 4, u = i & 15;
            CP_ASYNC16(w2u + (uint32_t)(r * LDX + u * 8) * 2, w24 + r * 16 + u);
        }
        CP_COMMIT();

        // ---- GEMM1: H[128x256] = relu(X @ W1 + b1) ; warp tile 32 x 64 ----
        FragC acc[2][4];
        int nbase = wn * 64;
        #pragma unroll
        for (int mi = 0; mi < 2; mi++)
            #pragma unroll
            for (int nt = 0; nt < 4; nt++)
                wmma::load_matrix_sync(acc[mi][nt], &b1T[nbase + nt * 16], 256, wmma::mem_row_major);

        #pragma unroll
        for (int ks = 0; ks < 8; ks++) {
            FragA a[2];
            #pragma unroll
            for (int mi = 0; mi < 2; mi++)
                wmma::load_matrix_sync(a[mi], &xr[(m0 + mi * 16) * LDX + ks * 16], LDX);
            #pragma unroll
            for (int nt = 0; nt < 4; nt++) {
                FragB b;
                wmma::load_matrix_sync(b, &w1[(ks * 16) * LDW + nbase + nt * 16], LDW);
                #pragma unroll
                for (int mi = 0; mi < 2; mi++)
                    wmma::mma_sync(acc[mi][nt], a[mi], b, acc[mi][nt]);
            }
        }

        // fragment-resident relu + fp16 convert -> H
        #pragma unroll
        for (int mi = 0; mi < 2; mi++)
            #pragma unroll
            for (int nt = 0; nt < 4; nt++) {
                FragCh hc;
                #pragma unroll
                for (int j = 0; j < acc[mi][nt].num_elements; j++) {
                    float v = acc[mi][nt].x[j];
                    hc.x[j] = __float2half_rn(v > 0.f ? v : 0.f);
                }
                wmma::store_matrix_sync(&hh[(m0 + mi * 16) * LDW + nbase + nt * 16],
                                        hc, LDW, wmma::mem_row_major);
            }
        __syncthreads();     // H visible; X fully consumed

        // ---- next tile meta + X prefetch into xr (hidden under GEMM2) ----
        int ntile = t + 1;
        if (ntile < tEnd && tid < 128) {
            int rs = g_tileStart[ntile], nr = g_tileRows[ntile];
            int tok = -1; float w = 0.f;
            if (tid < nr) { tok = g_rowToken[rs + tid]; w = g_rowW[rs + tid]; }
            tokS[nb][tid] = tok; wS[nb][tid] = w;
        }
        __syncthreads();     // tokS[nb] visible for prefetch addressing
        if (ntile < tEnd) {
            for (int i = tid; i < 128 * 16; i += NTHR) {
                int r = i >> 4, u = i & 15;
                int tok = tokS[nb][r]; if (tok < 0) tok = 0;
                CP_ASYNC16(xru + (uint32_t)(r * LDX + u * 8) * 2, x4 + (long)tok * 16 + u);
            }
        }
        CP_COMMIT();
        CP_WAIT1();          // W2 chunk0 arrived (X prefetch still in flight)
        __syncthreads();

        // ---- GEMM2 chunk0: acc2 = b2 + H[:,0:128] @ W2[0:128] ----
        FragC acc2[2][2];
        int nb2 = wn * 32;
        #pragma unroll
        for (int mi = 0; mi < 2; mi++)
            #pragma unroll
            for (int nt = 0; nt < 2; nt++)
                wmma::load_matrix_sync(acc2[mi][nt], &b2T[nb2 + nt * 16], 128, wmma::mem_row_major);

        #pragma unroll
        for (int ks = 0; ks < 8; ks++) {
            FragA a[2];
            #pragma unroll
            for (int mi = 0; mi < 2; mi++)
                wmma::load_matrix_sync(a[mi], &hh[(m0 + mi * 16) * LDW + ks * 16], LDW);
            #pragma unroll
            for (int nt = 0; nt < 2; nt++) {
                FragB b;
                wmma::load_matrix_sync(b, &w2c[(ks * 16) * LDX + nb2 + nt * 16], LDX);
                #pragma unroll
                for (int mi = 0; mi < 2; mi++)
                    wmma::mma_sync(acc2[mi][nt], a[mi], b, acc2[mi][nt]);
            }
        }
        __syncthreads();     // chunk0 consumed

        // ---- fill W2 chunk1 (serial) ----
        for (int i = tid; i < 128 * 16; i += NTHR) {
            int r = i >> 4, u = i & 15;
            *reinterpret_cast<uint4*>(&w2c[r * LDX + u * 8]) = w24[(128 + r) * 16 + u];
        }
        __syncthreads();

        // ---- GEMM2 chunk1 ----
        #pragma unroll
        for (int ks = 0; ks < 8; ks++) {
            FragA a[2];
            #pragma unroll
            for (int mi = 0; mi < 2; mi++)
                wmma::load_matrix_sync(a[mi], &hh[(m0 + mi * 16) * LDW + 128 + ks * 16], LDW);
            #pragma unroll
            for (int nt = 0; nt < 2; nt++) {
                FragB b;
                wmma::load_matrix_sync(b, &w2c[(ks * 16) * LDX + nb2 + nt * 16], LDX);
                #pragma unroll
                for (int mi = 0; mi < 2; mi++)
                    wmma::mma_sync(acc2[mi][nt], a[mi], b, acc2[mi][nt]);
            }
        }
        __syncthreads();     // H reads done; hh reusable as fp32 stage

        // ---- epilogue: stage C over dead H region, weighted atomics ----
        #pragma unroll
        for (int mi = 0; mi < 2; mi++)
            #pragma unroll
            for (int nt = 0; nt < 2; nt++)
                wmma::store_matrix_sync(&stC[(m0 + mi * 16) * 132 + nb2 + nt * 16],
                                        acc2[mi][nt], 132, wmma::mem_row_major);
        __syncthreads();

        #pragma unroll 2
        for (int i = tid; i < 128 * DIM_OUT; i += NTHR) {
            int r = i >> 7, c = i & 127;
            int tok = tokS[buf][r];
            if (tok >= 0)
                atomicAdd(&out[(long)tok * DIM_OUT + c], wS[buf][r] * stC[r * 132 + c]);
        }
    }
}

// ---------------- launch ----------------
extern "C" void kernel_launch(void* const* d_in, const int* in_sizes, int n_in,
                              void* d_out, int out_size) {
    const float* x  = (const float*)d_in[0];
    const float* Wp = (const float*)d_in[1];
    const float* bp = (const float*)d_in[2];
    const float* Ee = (const float*)d_in[3];
    const float* W1 = (const float*)d_in[4];
    const float* b1 = (const float*)d_in[5];
    const float* W2 = (const float*)d_in[6];
    const float* b2 = (const float*)d_in[7];
    float* out = (float*)d_out;

    int n = in_sizes[0] / DIM_IN;

    float* pout = nullptr;
    long need = (long)n * DIM_OUT + (long)n * NEXP;
    long zlo = (long)n * DIM_OUT, zhi = (long)out_size;
    if ((long)out_size >= need) {
        pout = out + ((long)out_size - (long)n * NEXP);
        zhi = (long)out_size - (long)n * NEXP;
    }

    moe_prep<<<256, 256>>>(W1, W2);
    moe_gate<<<1024, 256>>>(x, Wp, bp, Ee, out, zlo, zhi, pout, n);
    moe_build<<<1, 1>>>();
    moe_scatter<<<(n + 255) / 256, 256>>>(n);

    cudaFuncSetAttribute(moe_expert, cudaFuncAttributeMaxDynamicSharedMemorySize, SMEM_EXP);
    moe_expert<<<152, NTHR, SMEM_EXP>>>(b1, b2, out);
}